// round 13
// baseline (speedup 1.0000x reference)
#include <cuda_runtime.h>
#include <cuda_bf16.h>

// GIN MessagePassing — round 11: HMMA bf16 hi/lo 3-pass.
// Single 512-thread CTA, BM=128, BN=256, BK=32, warp tile 32x64 (wm4 x wn4).
// Split-K=4 on K1 -> partials; reduce FUSED into K2's A-loader.
//   K1: part[sp] = adj[:, seg]@x[seg]
//   K2: h1 = relu(((1+eps)x + sum part)@W1 + b1)
//   K3: out = h1@W2 + b2

#define BM 128
#define BN 256
#define BK 32
#define STRD 80
#define A_T (128 * STRD)             // 10240
#define B_T (256 * STRD)             // 20480
#define OFF_ALO (A_T)
#define OFF_BHI (2 * A_T)
#define OFF_BLO (2 * A_T + B_T)
#define STAGE   (2 * A_T + 2 * B_T)  // 61440
#define SMEM_TOT (2 * STAGE)         // 122880 (1 CTA/SM)
#define PSTR (8LL * 4096 * 256)      // partial plane stride

// ---------------- scratch ----------------
__device__ float g_h1[8u * 4096u * 512u];
__device__ float g_part[4u * 8u * 4096u * 256u];
__device__ __align__(16) __nv_bfloat16 g_Bx_hi[8u * 256u * 4096u];
__device__ __align__(16) __nv_bfloat16 g_Bx_lo[8u * 256u * 4096u];
__device__ __align__(16) __nv_bfloat16 g_W1_hi[512u * 256u];
__device__ __align__(16) __nv_bfloat16 g_W1_lo[512u * 256u];
__device__ __align__(16) __nv_bfloat16 g_W2_hi[256u * 512u];
__device__ __align__(16) __nv_bfloat16 g_W2_lo[256u * 512u];

__device__ __forceinline__ unsigned s2u(const void* p) {
    unsigned a;
    asm("{ .reg .u64 t; cvta.to.shared.u64 t, %1; cvt.u32.u64 %0, t; }"
        : "=r"(a) : "l"(p));
    return a;
}
__device__ __forceinline__ void ldsm4(unsigned r[4], unsigned a) {
    asm volatile("ldmatrix.sync.aligned.m8n8.x4.shared.b16 {%0,%1,%2,%3}, [%4];"
                 : "=r"(r[0]), "=r"(r[1]), "=r"(r[2]), "=r"(r[3]) : "r"(a));
}
__device__ __forceinline__ void mma16816(float c[4], const unsigned a[4],
                                         const unsigned b[2]) {
    asm volatile(
        "mma.sync.aligned.m16n8k16.row.col.f32.bf16.bf16.f32 "
        "{%0,%1,%2,%3},{%4,%5,%6,%7},{%8,%9},{%0,%1,%2,%3};"
        : "+f"(c[0]), "+f"(c[1]), "+f"(c[2]), "+f"(c[3])
        : "r"(a[0]), "r"(a[1]), "r"(a[2]), "r"(a[3]), "r"(b[0]), "r"(b[1]));
}
__device__ __forceinline__ void cpa16(unsigned dst, const void* src) {
    asm volatile("cp.async.ca.shared.global [%0], [%1], 16;"
                 :: "r"(dst), "l"(src) : "memory");
}
__device__ __forceinline__ unsigned pack2bf(float x, float y) {
    const __nv_bfloat16 bx = __float2bfloat16(x), by = __float2bfloat16(y);
    return (unsigned)__bfloat16_as_ushort(bx) |
           ((unsigned)__bfloat16_as_ushort(by) << 16);
}

// ---------------- pack: [K,N] fp32 -> [N,K] bf16 hi/lo ----------------
__global__ __launch_bounds__(256)
void pack_bt(const float* __restrict__ in, __nv_bfloat16* __restrict__ ohi,
             __nv_bfloat16* __restrict__ olo, int K, int N)
{
    __shared__ float t[32][33];
    const int b = blockIdx.z;
    const float* ib = in + (long long)b * K * N;
    const int k0 = blockIdx.x * 32, n0 = blockIdx.y * 32;
    const int tx = threadIdx.x, ty = threadIdx.y;
#pragma unroll
    for (int i = 0; i < 4; ++i)
        t[ty + i * 8][tx] = ib[(long long)(k0 + ty + i * 8) * N + n0 + tx];
    __syncthreads();
    __nv_bfloat16* oh = ohi + (long long)b * K * N;
    __nv_bfloat16* ol = olo + (long long)b * K * N;
#pragma unroll
    for (int i = 0; i < 4; ++i) {
        const int n = n0 + ty + i * 8, k = k0 + tx;
        const float v = t[tx][ty + i * 8];
        const __nv_bfloat16 h = __float2bfloat16(v);
        const __nv_bfloat16 l = __float2bfloat16(v - __bfloat162float(h));
        oh[(long long)n * K + k] = h;
        ol[(long long)n * K + k] = l;
    }
}

// ---------------- HMMA GEMM: 16 warps, warp tile 32x64 ----------------
// EPI 1: A=adj fp32, C=partials.  EPI 2: A composed ((1+eps)x + 4 partials),
// C=h1 bias+relu.  EPI 3: A=h1 fp32, C=out bias.
template<int EPI>
__global__ __launch_bounds__(512, 1)
void gemm6(const float* __restrict__ A,
           const __nv_bfloat16* __restrict__ Bhi,
           const __nv_bfloat16* __restrict__ Blo,
           float* __restrict__ C,
           const float* __restrict__ bias,
           const float* __restrict__ part,    // EPI==2
           const float* __restrict__ epsp,    // EPI==2
           int lda, int ldC, int kseg,
           long long sA, long long sB, long long sC)
{
    extern __shared__ char smem[];
    const int tid  = threadIdx.x;
    const int wid  = tid >> 5;
    const int lane = tid & 31;
    const int wm   = wid & 3;        // 4 warps in M (32 rows)
    const int wn   = wid >> 2;       // 4 warps in N (64 cols)

    const int zz  = blockIdx.z;
    const int bz  = (EPI == 1) ? (zz >> 2) : zz;
    const int sp  = (EPI == 1) ? (zz & 3) : 0;
    const int k0s = sp * kseg;
    const int n0  = blockIdx.x * BN;
    const long long row0 = (long long)blockIdx.y * BM;

    const float* Ap = A + (long long)bz * sA + row0 * lda;
    const float* Pp = (EPI == 2) ? (part + row0 * lda) : nullptr;
    const __nv_bfloat16* Bh = Bhi + (long long)bz * sB + (long long)n0 * lda;
    const __nv_bfloat16* Bl = Blo + (long long)bz * sB + (long long)n0 * lda;

    float ev = 0.f;
    if (EPI == 2) ev = 1.0f + epsp[0];

    const unsigned sbase = s2u(smem);

    // A: 128 rows x 32 fp32; thread -> row tid>>2, 8-col group (tid&3)*8
    const int ar  = tid >> 2;
    const int ac0 = (tid & 3) * 8;
    float4 pa[2];
    auto ldA = [&](int k0) {
        const long long o = (long long)ar * lda + k0 + ac0;
        pa[0] = *(const float4*)(Ap + o);
        pa[1] = *(const float4*)(Ap + o + 4);
        if (EPI == 2) {
            pa[0].x *= ev; pa[0].y *= ev; pa[0].z *= ev; pa[0].w *= ev;
            pa[1].x *= ev; pa[1].y *= ev; pa[1].z *= ev; pa[1].w *= ev;
#pragma unroll
            for (int s = 0; s < 4; ++s) {
                const float4 q0 = *(const float4*)(Pp + s * PSTR + o);
                const float4 q1 = *(const float4*)(Pp + s * PSTR + o + 4);
                pa[0].x += q0.x; pa[0].y += q0.y; pa[0].z += q0.z; pa[0].w += q0.w;
                pa[1].x += q1.x; pa[1].y += q1.y; pa[1].z += q1.z; pa[1].w += q1.w;
            }
        }
    };
    auto stA = [&](int s) {
        const float f[8] = {pa[0].x, pa[0].y, pa[0].z, pa[0].w,
                            pa[1].x, pa[1].y, pa[1].z, pa[1].w};
        unsigned hi[4], lo[4];
#pragma unroll
        for (int q = 0; q < 4; ++q) {
            const float a = f[2 * q], b = f[2 * q + 1];
            const float ra = a - __bfloat162float(__float2bfloat16(a));
            const float rb = b - __bfloat162float(__float2bfloat16(b));
            hi[q] = pack2bf(a, b);
            lo[q] = pack2bf(ra, rb);
        }
        char* base = smem + s * STAGE;
        const unsigned off = (unsigned)(ar * STRD + ac0 * 2);
        *(uint4*)(base + off)           = make_uint4(hi[0], hi[1], hi[2], hi[3]);
        *(uint4*)(base + OFF_ALO + off) = make_uint4(lo[0], lo[1], lo[2], lo[3]);
    };
    // B: 256 rows x 32 bf16 per plane; thread -> row tid>>1, 16B half (tid&1)
    const int br = tid >> 1;
    const int bh2 = (tid & 1) * 32;
    auto cpB = [&](int s, int k0) {
        const unsigned d = sbase + s * STAGE + br * STRD + bh2;
        const long long so = (long long)br * lda + k0 + (bh2 >> 1);
        cpa16(d + OFF_BHI,      Bh + so);
        cpa16(d + OFF_BHI + 16, Bh + so + 8);
        cpa16(d + OFF_BLO,      Bl + so);
        cpa16(d + OFF_BLO + 16, Bl + so + 8);
        asm volatile("cp.async.commit_group;" ::: "memory");
    };

    // ---- prologue ----
    cpB(0, k0s);
    ldA(k0s);
    stA(0);
    asm volatile("cp.async.wait_group 0;" ::: "memory");
    __syncthreads();

    float acc[2][8][4];
#pragma unroll
    for (int i = 0; i < 2; ++i)
#pragma unroll
        for (int j = 0; j < 8; ++j)
#pragma unroll
            for (int e = 0; e < 4; ++e) acc[i][j][e] = 0.f;

    const int lrow = lane & 7, quad = lane >> 3;
    const unsigned aoff =
        (unsigned)((wm * 32 + lrow + (quad & 1) * 8) * STRD + ((quad >> 1) * 8) * 2);
    const unsigned boff =
        (unsigned)((wn * 64 + lrow + (quad >> 1) * 8) * STRD + ((quad & 1) * 8) * 2);

    const int nIter = kseg >> 5;
    for (int it = 0; it < nIter; ++it) {
        const int s = it & 1;
        const unsigned sb = sbase + s * STAGE;
        const bool more = (it + 1 < nIter);
        if (more) { cpB(s ^ 1, k0s + (it + 1) * BK); ldA(k0s + (it + 1) * BK); }

#pragma unroll
        for (int k2 = 0; k2 < 2; ++k2) {
            const unsigned kb = (unsigned)(k2 * 32);
            unsigned b_hi[4][4], a_hi[2][4];
#pragma unroll
            for (int p = 0; p < 4; ++p)
                ldsm4(b_hi[p], sb + OFF_BHI + boff + p * 16 * STRD + kb);
#pragma unroll
            for (int i = 0; i < 2; ++i)
                ldsm4(a_hi[i], sb + aoff + i * 16 * STRD + kb);
            // pass 1: hi*hi
#pragma unroll
            for (int i = 0; i < 2; ++i)
#pragma unroll
                for (int p = 0; p < 4; ++p) {
                    mma16816(acc[i][2 * p + 0], a_hi[i], b_hi[p] + 0);
                    mma16816(acc[i][2 * p + 1], a_hi[i], b_hi[p] + 2);
                }
            // pass 2: lo*hi (a_lo transient)
            {
                unsigned a_lo[2][4];
#pragma unroll
                for (int i = 0; i < 2; ++i)
                    ldsm4(a_lo[i], sb + OFF_ALO + aoff + i * 16 * STRD + kb);
#pragma unroll
                for (int i = 0; i < 2; ++i)
#pragma unroll
                    for (int p = 0; p < 4; ++p) {
                        mma16816(acc[i][2 * p + 0], a_lo[i], b_hi[p] + 0);
                        mma16816(acc[i][2 * p + 1], a_lo[i], b_hi[p] + 2);
                    }
            }
            // pass 3: hi*lo (b_lo transient, per n16 tile)
#pragma unroll
            for (int p = 0; p < 4; ++p) {
                unsigned b_lo[4];
                ldsm4(b_lo, sb + OFF_BLO + boff + p * 16 * STRD + kb);
#pragma unroll
                for (int i = 0; i < 2; ++i) {
                    mma16816(acc[i][2 * p + 0], a_hi[i], b_lo + 0);
                    mma16816(acc[i][2 * p + 1], a_hi[i], b_lo + 2);
                }
            }
        }
        if (more) {
            stA(s ^ 1);
            asm volatile("cp.async.wait_group 0;" ::: "memory");
        }
        __syncthreads();
    }

    // ---- epilogue ----
    const int r4 = lane >> 2, c2 = (lane & 3) * 2;
    float* Cb = C + (long long)((EPI == 1) ? (sp * 8 + bz) : bz) * sC;

#pragma unroll
    for (int i = 0; i < 2; ++i) {
        const long long rg0 = row0 + wm * 32 + i * 16 + r4;
#pragma unroll
        for (int j = 0; j < 8; ++j) {
            const int cg = n0 + wn * 64 + j * 8 + c2;
            float2 v0 = make_float2(acc[i][j][0], acc[i][j][1]);
            float2 v1 = make_float2(acc[i][j][2], acc[i][j][3]);
            if (EPI == 2) {
                const float bx = bias[cg], by = bias[cg + 1];
                v0.x = fmaxf(v0.x + bx, 0.f); v0.y = fmaxf(v0.y + by, 0.f);
                v1.x = fmaxf(v1.x + bx, 0.f); v1.y = fmaxf(v1.y + by, 0.f);
            } else if (EPI == 3) {
                const float bx = bias[cg], by = bias[cg + 1];
                v0.x += bx; v0.y += by;
                v1.x += bx; v1.y += by;
            }
            *(float2*)(Cb + rg0 * ldC + cg)       = v0;
            *(float2*)(Cb + (rg0 + 8) * ldC + cg) = v1;
        }
    }
}

extern "C" void kernel_launch(void* const* d_in, const int* in_sizes, int n_in,
                              void* d_out, int out_size)
{
    (void)in_sizes; (void)n_in; (void)out_size;
    const float* x   = (const float*)d_in[0];
    const float* adj = (const float*)d_in[1];
    const float* eps = (const float*)d_in[2];
    const float* W1  = (const float*)d_in[3];
    const float* b1  = (const float*)d_in[4];
    const float* W2  = (const float*)d_in[5];
    const float* b2  = (const float*)d_in[6];
    float* out = (float*)d_out;

    float *h1, *part;
    __nv_bfloat16 *bxh, *bxl, *w1h, *w1l, *w2h, *w2l;
    cudaGetSymbolAddress((void**)&h1,   g_h1);
    cudaGetSymbolAddress((void**)&part, g_part);
    cudaGetSymbolAddress((void**)&bxh,  g_Bx_hi);
    cudaGetSymbolAddress((void**)&bxl,  g_Bx_lo);
    cudaGetSymbolAddress((void**)&w1h,  g_W1_hi);
    cudaGetSymbolAddress((void**)&w1l,  g_W1_lo);
    cudaGetSymbolAddress((void**)&w2h,  g_W2_hi);
    cudaGetSymbolAddress((void**)&w2l,  g_W2_lo);

    cudaFuncSetAttribute(gemm6<1>, cudaFuncAttributeMaxDynamicSharedMemorySize, SMEM_TOT);
    cudaFuncSetAttribute(gemm6<2>, cudaFuncAttributeMaxDynamicSharedMemorySize, SMEM_TOT);
    cudaFuncSetAttribute(gemm6<3>, cudaFuncAttributeMaxDynamicSharedMemorySize, SMEM_TOT);

    const dim3 tb(32, 8);
    pack_bt<<<dim3(128, 8, 8), tb>>>(x,  bxh, bxl, 4096, 256);
    pack_bt<<<dim3(8, 16, 1),  tb>>>(W1, w1h, w1l, 256, 512);
    pack_bt<<<dim3(16, 8, 1),  tb>>>(W2, w2h, w2l, 512, 256);

    // K1: part[sp][b] = adj[b][:, seg]@x[b][seg]   (z = b*4 + sp), 1024 CTAs
    gemm6<1><<<dim3(1, 32, 32), 512, SMEM_TOT>>>(
        adj, bxh, bxl, part, nullptr, nullptr, nullptr,
        /*lda=*/4096, /*ldC=*/256, /*kseg=*/1024,
        4096LL * 4096, 256LL * 4096, 4096LL * 256);

    // K2: h1 = relu(((1+eps)x + sum part)@W1 + b1)   A composed in-loader
    gemm6<2><<<dim3(2, 256, 1), 512, SMEM_TOT>>>(
        x, w1h, w1l, h1, b1, part, eps,
        /*lda=*/256, /*ldC=*/512, /*kseg=*/256, 0, 0, 0);

    // K3: out = h1@W2 + b2
    gemm6<3><<<dim3(1, 256, 1), 512, SMEM_TOT>>>(
        h1, w2h, w2l, out, b2, nullptr, nullptr,
        /*lda=*/512, /*ldC=*/256, /*kseg=*/512, 0, 0, 0);
}

// round 15
// speedup vs baseline: 1.5096x; 1.5096x over previous
#include <cuda_runtime.h>
#include <cuda_bf16.h>
#include <cuda_fp16.h>

// GIN MessagePassing — round 14 (R13 + grid.x fix for K1).
// K1: fp16 hi/lo 2-pass HMMA, 512-thread CTA, 32x32 warp tiles, BM=BN=128,
//     split-K=4 -> partial planes.   *** grid (2,32,32): covers full N=256 ***
// K2: bf16 hi/lo 3-pass, reduce ((1+eps)x + sum partials) fused into A-loader.
// K3: bf16 hi/lo 3-pass.

#define BM 128
#define BN 128
#define BK 32
#define STRD 80
#define PL (128 * STRD)              // one 128-row plane = 10240 B

// K1 (fp16): planes Ahi, Alo, B
#define F_OFF_ALO (PL)
#define F_OFF_B   (2 * PL)
#define F_STAGE   (3 * PL)           // 30720
#define F_SMEM    (2 * F_STAGE)      // 61440

// K2/K3 (bf16): planes Ahi, Alo, Bhi, Blo
#define B_OFF_ALO (PL)
#define B_OFF_BHI (2 * PL)
#define B_OFF_BLO (3 * PL)
#define B_STAGE   (4 * PL)           // 40960
#define B_SMEM    (2 * B_STAGE)      // 81920

#define PSTR (8LL * 4096 * 256)

// ---------------- scratch ----------------
__device__ float g_h1[8u * 4096u * 512u];
__device__ float g_part[4u * 8u * 4096u * 256u];
__device__ __align__(16) __half g_Bx_h[8u * 256u * 4096u];
__device__ __align__(16) __nv_bfloat16 g_W1_hi[512u * 256u];
__device__ __align__(16) __nv_bfloat16 g_W1_lo[512u * 256u];
__device__ __align__(16) __nv_bfloat16 g_W2_hi[256u * 512u];
__device__ __align__(16) __nv_bfloat16 g_W2_lo[256u * 512u];

__device__ __forceinline__ unsigned s2u(const void* p) {
    unsigned a;
    asm("{ .reg .u64 t; cvta.to.shared.u64 t, %1; cvt.u32.u64 %0, t; }"
        : "=r"(a) : "l"(p));
    return a;
}
__device__ __forceinline__ void ldsm4(unsigned r[4], unsigned a) {
    asm volatile("ldmatrix.sync.aligned.m8n8.x4.shared.b16 {%0,%1,%2,%3}, [%4];"
                 : "=r"(r[0]), "=r"(r[1]), "=r"(r[2]), "=r"(r[3]) : "r"(a));
}
__device__ __forceinline__ void mma_bf(float c[4], const unsigned a[4],
                                       const unsigned b[2]) {
    asm volatile(
        "mma.sync.aligned.m16n8k16.row.col.f32.bf16.bf16.f32 "
        "{%0,%1,%2,%3},{%4,%5,%6,%7},{%8,%9},{%0,%1,%2,%3};"
        : "+f"(c[0]), "+f"(c[1]), "+f"(c[2]), "+f"(c[3])
        : "r"(a[0]), "r"(a[1]), "r"(a[2]), "r"(a[3]), "r"(b[0]), "r"(b[1]));
}
__device__ __forceinline__ void mma_h(float c[4], const unsigned a[4],
                                      const unsigned b[2]) {
    asm volatile(
        "mma.sync.aligned.m16n8k16.row.col.f32.f16.f16.f32 "
        "{%0,%1,%2,%3},{%4,%5,%6,%7},{%8,%9},{%0,%1,%2,%3};"
        : "+f"(c[0]), "+f"(c[1]), "+f"(c[2]), "+f"(c[3])
        : "r"(a[0]), "r"(a[1]), "r"(a[2]), "r"(a[3]), "r"(b[0]), "r"(b[1]));
}
__device__ __forceinline__ void cpa16(unsigned dst, const void* src) {
    asm volatile("cp.async.ca.shared.global [%0], [%1], 16;"
                 :: "r"(dst), "l"(src) : "memory");
}
__device__ __forceinline__ unsigned pack2bf(float x, float y) {
    const __nv_bfloat16 bx = __float2bfloat16(x), by = __float2bfloat16(y);
    return (unsigned)__bfloat16_as_ushort(bx) |
           ((unsigned)__bfloat16_as_ushort(by) << 16);
}
__device__ __forceinline__ unsigned pack2h(float x, float y) {
    const __half hx = __float2half(x), hy = __float2half(y);
    return (unsigned)__half_as_ushort(hx) |
           ((unsigned)__half_as_ushort(hy) << 16);
}

// ---------------- pack x: [B][K=4096][N=256] fp32 -> [B][N][K] fp16 ----------------
__global__ __launch_bounds__(256)
void pack_x_h(const float* __restrict__ in, __half* __restrict__ o)
{
    __shared__ float t[32][33];
    const int b = blockIdx.z, K = 4096, N = 256;
    const float* ib = in + (long long)b * K * N;
    const int k0 = blockIdx.x * 32, n0 = blockIdx.y * 32;
    const int tx = threadIdx.x, ty = threadIdx.y;
#pragma unroll
    for (int i = 0; i < 4; ++i)
        t[ty + i * 8][tx] = ib[(long long)(k0 + ty + i * 8) * N + n0 + tx];
    __syncthreads();
    __half* ob = o + (long long)b * K * N;
#pragma unroll
    for (int i = 0; i < 4; ++i)
        ob[(long long)(n0 + ty + i * 8) * K + k0 + tx] =
            __float2half(t[tx][ty + i * 8]);
}

// ---------------- pack W: [K][N] fp32 -> [N][K] bf16 hi/lo ----------------
__global__ __launch_bounds__(256)
void pack_bt(const float* __restrict__ in, __nv_bfloat16* __restrict__ ohi,
             __nv_bfloat16* __restrict__ olo, int K, int N)
{
    __shared__ float t[32][33];
    const int k0 = blockIdx.x * 32, n0 = blockIdx.y * 32;
    const int tx = threadIdx.x, ty = threadIdx.y;
#pragma unroll
    for (int i = 0; i < 4; ++i)
        t[ty + i * 8][tx] = in[(long long)(k0 + ty + i * 8) * N + n0 + tx];
    __syncthreads();
#pragma unroll
    for (int i = 0; i < 4; ++i) {
        const int n = n0 + ty + i * 8, k = k0 + tx;
        const float v = t[tx][ty + i * 8];
        const __nv_bfloat16 h = __float2bfloat16(v);
        const __nv_bfloat16 l = __float2bfloat16(v - __bfloat162float(h));
        ohi[(long long)n * K + k] = h;
        olo[(long long)n * K + k] = l;
    }
}

// ================= K1: fp16 2-pass, split-K=4 partial store =================
__global__ __launch_bounds__(512, 1)
void gemm_k1(const float* __restrict__ A, const __half* __restrict__ Bx,
             float* __restrict__ C, int lda, int ldC, int kseg,
             long long sA, long long sB, long long sC)
{
    extern __shared__ char smem[];
    const int tid  = threadIdx.x;
    const int wid  = tid >> 5;
    const int lane = tid & 31;
    const int wm   = wid & 3;
    const int wn   = wid >> 2;

    const int zz  = blockIdx.z;
    const int bz  = zz >> 2;
    const int sp  = zz & 3;
    const int k0s = sp * kseg;
    const int n0  = blockIdx.x * BN;
    const long long row0 = (long long)blockIdx.y * BM;

    const float* Ap = A + (long long)bz * sA + row0 * lda;
    const __half* Bp = Bx + (long long)bz * sB + (long long)n0 * lda;

    const unsigned sbase = s2u(smem);

    const int ar  = tid >> 2;
    const int ac0 = (tid & 3) * 8;
    float4 pa[2];
    auto ldA = [&](int k0) {
        const float* p = Ap + (long long)ar * lda + k0 + ac0;
        pa[0] = *(const float4*)(p);
        pa[1] = *(const float4*)(p + 4);
    };
    auto stA = [&](int s) {
        const float f[8] = {pa[0].x, pa[0].y, pa[0].z, pa[0].w,
                            pa[1].x, pa[1].y, pa[1].z, pa[1].w};
        unsigned hi[4], lo[4];
#pragma unroll
        for (int q = 0; q < 4; ++q) {
            const float a = f[2 * q], b = f[2 * q + 1];
            const float ra = a - __half2float(__float2half(a));
            const float rb = b - __half2float(__float2half(b));
            hi[q] = pack2h(a, b);
            lo[q] = pack2h(ra, rb);
        }
        char* base = smem + s * F_STAGE;
        const unsigned off = (unsigned)(ar * STRD + ac0 * 2);
        *(uint4*)(base + off)             = make_uint4(hi[0], hi[1], hi[2], hi[3]);
        *(uint4*)(base + F_OFF_ALO + off) = make_uint4(lo[0], lo[1], lo[2], lo[3]);
    };
    const int br = tid >> 2;
    const int bc = tid & 3;
    auto cpB = [&](int s, int k0) {
        const unsigned d = sbase + s * F_STAGE + F_OFF_B + br * STRD + bc * 16;
        cpa16(d, Bp + (long long)br * lda + k0 + bc * 8);
        asm volatile("cp.async.commit_group;" ::: "memory");
    };

    ldA(k0s);
    cpB(0, k0s);
    stA(0);
    asm volatile("cp.async.wait_group 0;" ::: "memory");
    __syncthreads();

    float acc[2][4][4];
#pragma unroll
    for (int i = 0; i < 2; ++i)
#pragma unroll
        for (int j = 0; j < 4; ++j)
#pragma unroll
            for (int e = 0; e < 4; ++e) acc[i][j][e] = 0.f;

    const int lrow = lane & 7, quad = lane >> 3;
    const unsigned aoff =
        (unsigned)((wm * 32 + lrow + (quad & 1) * 8) * STRD + ((quad >> 1) * 8) * 2);
    const unsigned boff =
        (unsigned)((wn * 32 + lrow + (quad >> 1) * 8) * STRD + ((quad & 1) * 8) * 2);

    const int nIter = kseg >> 5;
    for (int it = 0; it < nIter; ++it) {
        const int s = it & 1;
        const unsigned sb = sbase + s * F_STAGE;
        const bool more = (it + 1 < nIter);
        if (more) { ldA(k0s + (it + 1) * BK); cpB(s ^ 1, k0s + (it + 1) * BK); }

#pragma unroll
        for (int k2 = 0; k2 < 2; ++k2) {
            const unsigned kb = (unsigned)(k2 * 32);
            unsigned a_hi[2][4], a_lo[2][4];
#pragma unroll
            for (int i = 0; i < 2; ++i) {
                ldsm4(a_hi[i], sb + aoff + i * 16 * STRD + kb);
                ldsm4(a_lo[i], sb + F_OFF_ALO + aoff + i * 16 * STRD + kb);
            }
#pragma unroll
            for (int p = 0; p < 2; ++p) {
                unsigned bfr[4];
                ldsm4(bfr, sb + F_OFF_B + boff + p * 16 * STRD + kb);
#pragma unroll
                for (int i = 0; i < 2; ++i) {
                    mma_h(acc[i][2 * p + 0], a_hi[i], bfr + 0);
                    mma_h(acc[i][2 * p + 1], a_hi[i], bfr + 2);
                    mma_h(acc[i][2 * p + 0], a_lo[i], bfr + 0);
                    mma_h(acc[i][2 * p + 1], a_lo[i], bfr + 2);
                }
            }
        }
        if (more) {
            stA(s ^ 1);
            asm volatile("cp.async.wait_group 0;" ::: "memory");
        }
        __syncthreads();
    }

    const int r4 = lane >> 2, c2 = (lane & 3) * 2;
    float* Cb = C + (long long)(sp * 8 + bz) * sC;
#pragma unroll
    for (int i = 0; i < 2; ++i) {
        const long long rg0 = row0 + wm * 32 + i * 16 + r4;
#pragma unroll
        for (int j = 0; j < 4; ++j) {
            const int cg = n0 + wn * 32 + j * 8 + c2;
            *(float2*)(Cb + rg0 * ldC + cg) =
                make_float2(acc[i][j][0], acc[i][j][1]);
            *(float2*)(Cb + (rg0 + 8) * ldC + cg) =
                make_float2(acc[i][j][2], acc[i][j][3]);
        }
    }
}

// ================= K2/K3: bf16 3-pass =================
template<int EPI>   // 2: compose+(bias,relu)   3: bias
__global__ __launch_bounds__(512, 1)
void gemm_bf(const float* __restrict__ A,
             const __nv_bfloat16* __restrict__ Bhi,
             const __nv_bfloat16* __restrict__ Blo,
             float* __restrict__ C,
             const float* __restrict__ bias,
             const float* __restrict__ part,
             const float* __restrict__ epsp,
             int lda, int ldC, int kseg)
{
    extern __shared__ char smem[];
    const int tid  = threadIdx.x;
    const int wid  = tid >> 5;
    const int lane = tid & 31;
    const int wm   = wid & 3;
    const int wn   = wid >> 2;

    const int n0  = blockIdx.x * BN;
    const long long row0 = (long long)blockIdx.y * BM;

    const float* Ap = A + row0 * lda;
    const float* Pp = (EPI == 2) ? (part + row0 * lda) : nullptr;
    const __nv_bfloat16* Bh = Bhi + (long long)n0 * lda;
    const __nv_bfloat16* Bl = Blo + (long long)n0 * lda;

    float ev = 0.f;
    if (EPI == 2) ev = 1.0f + epsp[0];

    const unsigned sbase = s2u(smem);

    const int ar  = tid >> 2;
    const int ac0 = (tid & 3) * 8;
    float4 pa[2];
    auto ldA = [&](int k0) {
        const long long o = (long long)ar * lda + k0 + ac0;
        pa[0] = *(const float4*)(Ap + o);
        pa[1] = *(const float4*)(Ap + o + 4);
        if (EPI == 2) {
            pa[0].x *= ev; pa[0].y *= ev; pa[0].z *= ev; pa[0].w *= ev;
            pa[1].x *= ev; pa[1].y *= ev; pa[1].z *= ev; pa[1].w *= ev;
#pragma unroll
            for (int s = 0; s < 4; ++s) {
                const float4 q0 = *(const float4*)(Pp + s * PSTR + o);
                const float4 q1 = *(const float4*)(Pp + s * PSTR + o + 4);
                pa[0].x += q0.x; pa[0].y += q0.y; pa[0].z += q0.z; pa[0].w += q0.w;
                pa[1].x += q1.x; pa[1].y += q1.y; pa[1].z += q1.z; pa[1].w += q1.w;
            }
        }
    };
    auto stA = [&](int s) {
        const float f[8] = {pa[0].x, pa[0].y, pa[0].z, pa[0].w,
                            pa[1].x, pa[1].y, pa[1].z, pa[1].w};
        unsigned hi[4], lo[4];
#pragma unroll
        for (int q = 0; q < 4; ++q) {
            const float a = f[2 * q], b = f[2 * q + 1];
            const float ra = a - __bfloat162float(__float2bfloat16(a));
            const float rb = b - __bfloat162float(__float2bfloat16(b));
            hi[q] = pack2bf(a, b);
            lo[q] = pack2bf(ra, rb);
        }
        char* base = smem + s * B_STAGE;
        const unsigned off = (unsigned)(ar * STRD + ac0 * 2);
        *(uint4*)(base + off)             = make_uint4(hi[0], hi[1], hi[2], hi[3]);
        *(uint4*)(base + B_OFF_ALO + off) = make_uint4(lo[0], lo[1], lo[2], lo[3]);
    };
    const int br = tid >> 2;
    const int bc = tid & 3;
    auto cpB = [&](int s, int k0) {
        const unsigned d = sbase + s * B_STAGE + br * STRD + bc * 16;
        const long long so = (long long)br * lda + k0 + bc * 8;
        cpa16(d + B_OFF_BHI, Bh + so);
        cpa16(d + B_OFF_BLO, Bl + so);
        asm volatile("cp.async.commit_group;" ::: "memory");
    };

    ldA(0);
    cpB(0, 0);
    stA(0);
    asm volatile("cp.async.wait_group 0;" ::: "memory");
    __syncthreads();

    float acc[2][4][4];
#pragma unroll
    for (int i = 0; i < 2; ++i)
#pragma unroll
        for (int j = 0; j < 4; ++j)
#pragma unroll
            for (int e = 0; e < 4; ++e) acc[i][j][e] = 0.f;

    const int lrow = lane & 7, quad = lane >> 3;
    const unsigned aoff =
        (unsigned)((wm * 32 + lrow + (quad & 1) * 8) * STRD + ((quad >> 1) * 8) * 2);
    const unsigned boff =
        (unsigned)((wn * 32 + lrow + (quad >> 1) * 8) * STRD + ((quad & 1) * 8) * 2);

    const int nIter = kseg >> 5;
    for (int it = 0; it < nIter; ++it) {
        const int s = it & 1;
        const unsigned sb = sbase + s * B_STAGE;
        const bool more = (it + 1 < nIter);
        if (more) { ldA((it + 1) * BK); cpB(s ^ 1, (it + 1) * BK); }

#pragma unroll
        for (int k2 = 0; k2 < 2; ++k2) {
            const unsigned kb = (unsigned)(k2 * 32);
            unsigned a_hi[2][4], a_lo[2][4];
#pragma unroll
            for (int i = 0; i < 2; ++i) {
                ldsm4(a_hi[i], sb + aoff + i * 16 * STRD + kb);
                ldsm4(a_lo[i], sb + B_OFF_ALO + aoff + i * 16 * STRD + kb);
            }
#pragma unroll
            for (int p = 0; p < 2; ++p) {
                unsigned b_hi[4], b_lo[4];
                ldsm4(b_hi, sb + B_OFF_BHI + boff + p * 16 * STRD + kb);
                ldsm4(b_lo, sb + B_OFF_BLO + boff + p * 16 * STRD + kb);
#pragma unroll
                for (int i = 0; i < 2; ++i) {
                    mma_bf(acc[i][2 * p + 0], a_hi[i], b_hi + 0);
                    mma_bf(acc[i][2 * p + 1], a_hi[i], b_hi + 2);
                    mma_bf(acc[i][2 * p + 0], a_hi[i], b_lo + 0);
                    mma_bf(acc[i][2 * p + 1], a_hi[i], b_lo + 2);
                    mma_bf(acc[i][2 * p + 0], a_lo[i], b_hi + 0);
                    mma_bf(acc[i][2 * p + 1], a_lo[i], b_hi + 2);
                }
            }
        }
        if (more) {
            stA(s ^ 1);
            asm volatile("cp.async.wait_group 0;" ::: "memory");
        }
        __syncthreads();
    }

    const int r4 = lane >> 2, c2 = (lane & 3) * 2;
#pragma unroll
    for (int i = 0; i < 2; ++i) {
        const long long rg0 = row0 + wm * 32 + i * 16 + r4;
#pragma unroll
        for (int j = 0; j < 4; ++j) {
            const int cg = n0 + wn * 32 + j * 8 + c2;
            float2 v0 = make_float2(acc[i][j][0], acc[i][j][1]);
            float2 v1 = make_float2(acc[i][j][2], acc[i][j][3]);
            const float bx = bias[cg], by = bias[cg + 1];
            if (EPI == 2) {
                v0.x = fmaxf(v0.x + bx, 0.f); v0.y = fmaxf(v0.y + by, 0.f);
                v1.x = fmaxf(v1.x + bx, 0.f); v1.y = fmaxf(v1.y + by, 0.f);
            } else {
                v0.x += bx; v0.y += by;
                v1.x += bx; v1.y += by;
            }
            *(float2*)(C + rg0 * ldC + cg)       = v0;
            *(float2*)(C + (rg0 + 8) * ldC + cg) = v1;
        }
    }
}

extern "C" void kernel_launch(void* const* d_in, const int* in_sizes, int n_in,
                              void* d_out, int out_size)
{
    (void)in_sizes; (void)n_in; (void)out_size;
    const float* x   = (const float*)d_in[0];
    const float* adj = (const float*)d_in[1];
    const float* eps = (const float*)d_in[2];
    const float* W1  = (const float*)d_in[3];
    const float* b1  = (const float*)d_in[4];
    const float* W2  = (const float*)d_in[5];
    const float* b2  = (const float*)d_in[6];
    float* out = (float*)d_out;

    float *h1, *part;
    __half* bxh;
    __nv_bfloat16 *w1h, *w1l, *w2h, *w2l;
    cudaGetSymbolAddress((void**)&h1,   g_h1);
    cudaGetSymbolAddress((void**)&part, g_part);
    cudaGetSymbolAddress((void**)&bxh,  g_Bx_h);
    cudaGetSymbolAddress((void**)&w1h,  g_W1_hi);
    cudaGetSymbolAddress((void**)&w1l,  g_W1_lo);
    cudaGetSymbolAddress((void**)&w2h,  g_W2_hi);
    cudaGetSymbolAddress((void**)&w2l,  g_W2_lo);

    cudaFuncSetAttribute(gemm_k1,    cudaFuncAttributeMaxDynamicSharedMemorySize, F_SMEM);
    cudaFuncSetAttribute(gemm_bf<2>, cudaFuncAttributeMaxDynamicSharedMemorySize, B_SMEM);
    cudaFuncSetAttribute(gemm_bf<3>, cudaFuncAttributeMaxDynamicSharedMemorySize, B_SMEM);

    const dim3 tb(32, 8);
    pack_x_h<<<dim3(128, 8, 8), tb>>>(x, bxh);
    pack_bt<<<dim3(8, 16, 1),  tb>>>(W1, w1h, w1l, 256, 512);
    pack_bt<<<dim3(16, 8, 1),  tb>>>(W2, w2h, w2l, 512, 256);

    // K1: part[sp][b] = adj[b][:, seg]@x[b][seg]   fp16 2-pass
    // *** grid.x = 2 -> n0 covers 0..255 (this was the R13 bug) ***
    gemm_k1<<<dim3(2, 32, 32), 512, F_SMEM>>>(
        adj, bxh, part,
        /*lda=*/4096, /*ldC=*/256, /*kseg=*/1024,
        4096LL * 4096, 256LL * 4096, 4096LL * 256);

    // K2: h1 = relu(((1+eps)x + sum part)@W1 + b1)
    gemm_bf<2><<<dim3(4, 256, 1), 512, B_SMEM>>>(
        x, w1h, w1l, h1, b1, part, eps,
        /*lda=*/256, /*ldC=*/512, /*kseg=*/256);

    // K3: out = h1@W2 + b2
    gemm_bf<3><<<dim3(2, 256, 1), 512, B_SMEM>>>(
        h1, w2h, w2l, out, b2, nullptr, nullptr,
        /*lda=*/512, /*ldC=*/256, /*kseg=*/512);
}